// round 9
// baseline (speedup 1.0000x reference)
#include <cuda_runtime.h>

#define NP 300000
#define NC 10000
#define MAINT 320

// ---- scratch (device globals; zero-initialized at module load) ----
__device__ __align__(16) int g_count4[NC * 4];    // per (center,species); re-zeroed by scan
__device__ __align__(16) int g_soff[NC * 4 + 4];  // (center,species) segment offsets + sentinel
__device__ unsigned g_packed[NP];                 // (center<<18)|(species<<16)|rank
__device__ int g_order[NP];                       // pair index, sorted by (center,species)

// ---------------------------------------------------------------------------
// Histogram per (center,species) with fused int64/int32 detection (odd words
// of int64 index data are all zero; for int32 species 0..3, P(all zero)=4^-256).
// The atomicAdd return value is the pair's rank within its (c,s) bucket, so
// the scatter pass needs no atomics.
// ---------------------------------------------------------------------------
__global__ void hist_kernel(const int* __restrict__ dens,
                            const int* __restrict__ sp) {
    __shared__ int s_any;
    if (threadIdx.x == 0) s_any = 0;
    __syncthreads();
    if (threadIdx.x < 256) {
        int v = sp[2 * threadIdx.x + 1];
        if (v) atomicOr(&s_any, 1);
    }
    __syncthreads();
    int st = s_any ? 1 : 2;  // nonzero odd word -> int32 (stride 1)

    int p = blockIdx.x * blockDim.x + threadIdx.x;
    if (p < NP) {
        int c = dens[p * st];
        int s = sp[p * st] & 3;
        unsigned rank = (unsigned)atomicAdd(&g_count4[(c << 2) | s], 1);
        g_packed[p] = ((unsigned)c << 18) | ((unsigned)s << 16) | rank;
    }
}

// ---------------------------------------------------------------------------
// Single-block scan: per-center totals (int4 loads of the 4 species counts),
// exclusive scan over 10k centers, then write the 4 species sub-offsets per
// center (int4 store). Re-zeros g_count4 for the next graph replay.
// ---------------------------------------------------------------------------
__global__ __launch_bounds__(1024) void scan_kernel() {
    __shared__ int wsum[32];
    int t = threadIdx.x;
    const int PER = (NC + 1023) / 1024;  // 10
    int base = t * PER;

    int4 cnt[PER];
    int sum = 0;
#pragma unroll
    for (int k = 0; k < PER; k++) {
        int c = base + k;
        if (c < NC) {
            cnt[k] = ((const int4*)g_count4)[c];
            sum += cnt[k].x + cnt[k].y + cnt[k].z + cnt[k].w;
        } else {
            cnt[k] = make_int4(0, 0, 0, 0);
        }
    }
    int lane = t & 31, warp = t >> 5;
    int inc = sum;
#pragma unroll
    for (int off = 1; off < 32; off <<= 1) {
        int n = __shfl_up_sync(0xffffffffu, inc, off);
        if (lane >= off) inc += n;
    }
    if (lane == 31) wsum[warp] = inc;
    __syncthreads();
    if (warp == 0) {
        int v = wsum[lane];
#pragma unroll
        for (int off = 1; off < 32; off <<= 1) {
            int n = __shfl_up_sync(0xffffffffu, v, off);
            if (lane >= off) v += n;
        }
        wsum[lane] = v;
    }
    __syncthreads();
    int run = inc - sum + (warp ? wsum[warp - 1] : 0);  // exclusive prefix
#pragma unroll
    for (int k = 0; k < PER; k++) {
        int c = base + k;
        if (c < NC) {
            int4 o;
            o.x = run;
            o.y = o.x + cnt[k].x;
            o.z = o.y + cnt[k].y;
            o.w = o.z + cnt[k].z;
            ((int4*)g_soff)[c] = o;
            run = o.w + cnt[k].w;
            ((int4*)g_count4)[c] = make_int4(0, 0, 0, 0);  // ready for next replay
        }
    }
    if (t == 1023) g_soff[NC * 4] = run;
}

// ---------------------------------------------------------------------------
// Atomic-free scatter: position = soff[(c,s)] + rank.
// ---------------------------------------------------------------------------
__global__ void scatter_kernel() {
    int p = blockIdx.x * blockDim.x + threadIdx.x;
    if (p < NP) {
        unsigned e = g_packed[p];
        int c = e >> 18;
        int s = (e >> 16) & 3;
        int pos = g_soff[(c << 2) | s] + (int)(e & 0xFFFFu);
        g_order[pos] = p;
    }
}

// ---------------------------------------------------------------------------
// Main kernel: one CTA per center, 320 threads = 4 groups of 80. Each group's
// 80 float4 slots cover the 320-float pair row (l0: 0-4, l1: 5-19, l2: 20-44,
// l3: 45-79). Groups take EVEN quarters of the center's pair range (balanced);
// because the order array is sorted by species within the center, a quarter is
// at most 4 contiguous species segments, so we loop species explicitly with a
// fixed accumulator — no per-pair predication — and store each (group,species)
// partial exactly once into smem. Same R7 epilogue: 4-group reduce, W-combine,
// coalesced store.
// ---------------------------------------------------------------------------
__global__ __launch_bounds__(MAINT, 5) void main_kernel(
    const float4* __restrict__ v0, const float4* __restrict__ v1,
    const float4* __restrict__ v2, const float4* __restrict__ v3,
    const float* __restrict__ W, float* __restrict__ out) {
    __shared__ float acc[16 * 320];  // [group*4+species][320]
    __shared__ float sW[16];
    int tid = threadIdx.x;
    if (tid < 16) sW[tid] = W[tid];
    int center = blockIdx.x;

    int g = tid / 80;
    int slot = tid - g * 80;

    // species segment boundaries for this center: soff[c*4 .. c*4+4]
    int4 s4 = ((const int4*)g_soff)[center];
    int send = g_soff[center * 4 + 4];
    int seg[5] = {s4.x, s4.y, s4.z, s4.w, send};
    int start = seg[0], end = seg[4];

    const float4* base;
    int rowf4, loc;
    if (slot < 5)       { base = v0; rowf4 = 5;  loc = slot; }
    else if (slot < 20) { base = v1; rowf4 = 15; loc = slot - 5; }
    else if (slot < 45) { base = v2; rowf4 = 25; loc = slot - 20; }
    else                { base = v3; rowf4 = 35; loc = slot - 45; }

    // even quarter for this group
    int len = end - start;
    int q = len >> 2, rem = len & 3;
    int b0 = start + g * q + min(g, rem);
    int b1 = b0 + q + (g < rem ? 1 : 0);

    float4* accv = (float4*)acc;
#pragma unroll
    for (int s = 0; s < 4; s++) {
        int a0 = max(b0, seg[s]);
        int a1 = min(b1, seg[s + 1]);
        float4 r0 = make_float4(0.f, 0.f, 0.f, 0.f);
        float4 r1 = make_float4(0.f, 0.f, 0.f, 0.f);
        int j = a0;
        for (; j + 1 < a1; j += 2) {
            int p0 = g_order[j];
            int p1 = g_order[j + 1];
            float4 va = __ldg(base + (size_t)p0 * rowf4 + loc);
            float4 vb = __ldg(base + (size_t)p1 * rowf4 + loc);
            r0.x += va.x; r0.y += va.y; r0.z += va.z; r0.w += va.w;
            r1.x += vb.x; r1.y += vb.y; r1.z += vb.z; r1.w += vb.w;
        }
        if (j < a1) {
            int p0 = g_order[j];
            float4 va = __ldg(base + (size_t)p0 * rowf4 + loc);
            r0.x += va.x; r0.y += va.y; r0.z += va.z; r0.w += va.w;
        }
        r0.x += r1.x; r0.y += r1.y; r0.z += r1.z; r0.w += r1.w;
        accv[(g * 4 + s) * 80 + slot] = r0;
    }
    __syncthreads();

    // W-combine + coalesced store: 1280 outputs, 4 per thread.
    float* outc = out + (size_t)center * 1280;
    for (int o = tid; o < 1280; o += MAINT) {
        int l = (o >= 80) + (o >= 320) + (o >= 720);
        int off_out = (l == 0) ? 0 : (l == 1) ? 80 : (l == 2) ? 320 : 720;
        int off_in  = (l == 0) ? 0 : (l == 1) ? 20 : (l == 2) ? 80 : 180;
        int i = o - off_out;
        int n = i % 20;
        int d = (i / 20) & 3;
        int c = i / 80;
        int e = off_in + c * 20 + n;
        float sum = 0.f;
#pragma unroll
        for (int s = 0; s < 4; s++) {
            float a = acc[s * 320 + e] + acc[(4 + s) * 320 + e] +
                      acc[(8 + s) * 320 + e] + acc[(12 + s) * 320 + e];
            sum = fmaf(sW[d * 4 + s], a, sum);
        }
        outc[o] = sum;
    }
}

extern "C" void kernel_launch(void* const* d_in, const int* in_sizes, int n_in,
                              void* d_out, int out_size) {
    const float4* v0 = (const float4*)d_in[0];
    const float4* v1 = (const float4*)d_in[1];
    const float4* v2 = (const float4*)d_in[2];
    const float4* v3 = (const float4*)d_in[3];
    const float* W = (const float*)d_in[4];
    const int* sp = (const int*)d_in[5];
    const int* dens = (const int*)d_in[6];
    float* out = (float*)d_out;

    hist_kernel<<<(NP + 255) / 256, 256>>>(dens, sp);
    scan_kernel<<<1, 1024>>>();
    scatter_kernel<<<(NP + 255) / 256, 256>>>();
    main_kernel<<<NC, MAINT>>>(v0, v1, v2, v3, W, out);
}

// round 10
// speedup vs baseline: 1.2980x; 1.2980x over previous
#include <cuda_runtime.h>

#define NP 300000
#define NC 10000
#define MAINT 320

// ---- scratch (device globals; zero-initialized at module load) ----
__device__ int g_count[NC];          // re-zeroed by scan_kernel after use
__device__ int g_offsets[NC + 1];
__device__ unsigned g_packed[NP];    // (center<<18)|(species<<16)|rank
__device__ unsigned g_order[NP];     // (pair_index<<2)|species

// ---------------------------------------------------------------------------
// Histogram with fused int64/int32 detection. Odd 32-bit words of int64 index
// data (values < 2^31) are all zero; for int32 species values 0..3 the odds
// of 256 sampled words all being zero are 4^-256. The atomicAdd return value
// is the pair's rank within its center, so the scatter pass needs no atomics.
// ---------------------------------------------------------------------------
__global__ void hist_kernel(const int* __restrict__ dens,
                            const int* __restrict__ sp) {
    __shared__ int s_any;
    if (threadIdx.x == 0) s_any = 0;
    __syncthreads();
    if (threadIdx.x < 256) {
        int v = sp[2 * threadIdx.x + 1];
        if (v) atomicOr(&s_any, 1);
    }
    __syncthreads();
    int st = s_any ? 1 : 2;   // any nonzero odd word -> int32 (stride 1)

    int p = blockIdx.x * blockDim.x + threadIdx.x;
    if (p < NP) {
        int c = dens[p * st];
        int s = sp[p * st] & 3;
        unsigned rank = (unsigned)atomicAdd(&g_count[c], 1);
        g_packed[p] = ((unsigned)c << 18) | ((unsigned)s << 16) | rank;
    }
}

// ---------------------------------------------------------------------------
// Single-block exclusive scan over 10k counts; re-zeros g_count for the next
// graph replay (device globals are only auto-zeroed at module load).
// ---------------------------------------------------------------------------
__global__ __launch_bounds__(1024) void scan_kernel() {
    __shared__ int sc[NC];
    __shared__ int wsum[32];
    int t = threadIdx.x;
    for (int i = t; i < NC; i += 1024) sc[i] = g_count[i];
    __syncthreads();

    const int PER = (NC + 1023) / 1024;  // 10
    int base = t * PER;
    int local[PER];
    int sum = 0;
#pragma unroll
    for (int k = 0; k < PER; k++) {
        int i = base + k;
        int c = (i < NC) ? sc[i] : 0;
        local[k] = c;
        sum += c;
    }
    int lane = t & 31, warp = t >> 5;
    int inc = sum;
#pragma unroll
    for (int off = 1; off < 32; off <<= 1) {
        int n = __shfl_up_sync(0xffffffffu, inc, off);
        if (lane >= off) inc += n;
    }
    if (lane == 31) wsum[warp] = inc;
    __syncthreads();
    if (warp == 0) {
        int v = wsum[lane];
#pragma unroll
        for (int off = 1; off < 32; off <<= 1) {
            int n = __shfl_up_sync(0xffffffffu, v, off);
            if (lane >= off) v += n;
        }
        wsum[lane] = v;
    }
    __syncthreads();
    int run = inc - sum + (warp ? wsum[warp - 1] : 0);
#pragma unroll
    for (int k = 0; k < PER; k++) {
        int i = base + k;
        if (i < NC) {
            sc[i] = run;
            run += local[k];
        }
    }
    __syncthreads();
    for (int i = t; i < NC; i += 1024) {
        g_offsets[i] = sc[i];
        g_count[i] = 0;   // ready for next replay's hist
    }
    if (t == 1023) g_offsets[NC] = run;
}

// ---------------------------------------------------------------------------
// Atomic-free scatter: position = offsets[center] + rank (rank from hist).
// ---------------------------------------------------------------------------
__global__ void scatter_kernel() {
    int p = blockIdx.x * blockDim.x + threadIdx.x;
    if (p < NP) {
        unsigned e = g_packed[p];
        int c = e >> 18;
        int pos = g_offsets[c] + (int)(e & 0xFFFFu);
        g_order[pos] = ((unsigned)p << 2) | ((e >> 16) & 3u);
    }
}

// ---------------------------------------------------------------------------
// Main kernel (R7 structure + unroll-4 for MLP): one CTA per center, 320
// threads = 4 groups of 80. Each group's 80 float4 slots cover the 320-float
// pair row (l0: 0-4, l1: 5-19, l2: 20-44, l3: 45-79). Groups take even
// quarters of the center's pair range; 4 pairs in flight per thread,
// per-species register accumulation (predicated adds), then 4-group reduce +
// W-combine + coalesced store.
// ---------------------------------------------------------------------------
__global__ __launch_bounds__(MAINT, 4) void main_kernel(
    const float4* __restrict__ v0, const float4* __restrict__ v1,
    const float4* __restrict__ v2, const float4* __restrict__ v3,
    const float* __restrict__ W, float* __restrict__ out) {
    __shared__ float acc[16 * 320];  // [group*4+species][320]
    __shared__ float sW[16];
    int tid = threadIdx.x;
    if (tid < 16) sW[tid] = W[tid];
    int center = blockIdx.x;
    int start = g_offsets[center];
    int end = g_offsets[center + 1];

    int g = tid / 80;
    int slot = tid - g * 80;

    const float4* base;
    int rowf4, loc;
    if (slot < 5)       { base = v0; rowf4 = 5;  loc = slot; }
    else if (slot < 20) { base = v1; rowf4 = 15; loc = slot - 5; }
    else if (slot < 45) { base = v2; rowf4 = 25; loc = slot - 20; }
    else                { base = v3; rowf4 = 35; loc = slot - 45; }

    float4 r[4];
#pragma unroll
    for (int s = 0; s < 4; s++) r[s] = make_float4(0.f, 0.f, 0.f, 0.f);

    int len = end - start;
    int q = len >> 2, rem = len & 3;
    int b0 = start + g * q + min(g, rem);
    int b1 = b0 + q + (g < rem ? 1 : 0);

    int j = b0;
    for (; j + 3 < b1; j += 4) {
        unsigned e0 = g_order[j];
        unsigned e1 = g_order[j + 1];
        unsigned e2 = g_order[j + 2];
        unsigned e3 = g_order[j + 3];
        float4 va = __ldg(base + (size_t)(e0 >> 2) * rowf4 + loc);
        float4 vb = __ldg(base + (size_t)(e1 >> 2) * rowf4 + loc);
        float4 vc = __ldg(base + (size_t)(e2 >> 2) * rowf4 + loc);
        float4 vd = __ldg(base + (size_t)(e3 >> 2) * rowf4 + loc);
        int s0 = e0 & 3, s1 = e1 & 3, s2 = e2 & 3, s3 = e3 & 3;
#pragma unroll
        for (int k = 0; k < 4; k++) {
            if (s0 == k) { r[k].x += va.x; r[k].y += va.y; r[k].z += va.z; r[k].w += va.w; }
        }
#pragma unroll
        for (int k = 0; k < 4; k++) {
            if (s1 == k) { r[k].x += vb.x; r[k].y += vb.y; r[k].z += vb.z; r[k].w += vb.w; }
        }
#pragma unroll
        for (int k = 0; k < 4; k++) {
            if (s2 == k) { r[k].x += vc.x; r[k].y += vc.y; r[k].z += vc.z; r[k].w += vc.w; }
        }
#pragma unroll
        for (int k = 0; k < 4; k++) {
            if (s3 == k) { r[k].x += vd.x; r[k].y += vd.y; r[k].z += vd.z; r[k].w += vd.w; }
        }
    }
    for (; j < b1; j++) {
        unsigned e0 = g_order[j];
        float4 va = __ldg(base + (size_t)(e0 >> 2) * rowf4 + loc);
        int s0 = e0 & 3;
#pragma unroll
        for (int k = 0; k < 4; k++) {
            if (s0 == k) { r[k].x += va.x; r[k].y += va.y; r[k].z += va.z; r[k].w += va.w; }
        }
    }

    float4* accv = (float4*)acc;
#pragma unroll
    for (int s = 0; s < 4; s++)
        accv[(g * 4 + s) * 80 + slot] = r[s];
    __syncthreads();

    // W-combine + coalesced store: 1280 outputs, 4 per thread.
    float* outc = out + (size_t)center * 1280;
    for (int o = tid; o < 1280; o += MAINT) {
        int l = (o >= 80) + (o >= 320) + (o >= 720);
        int off_out = (l == 0) ? 0 : (l == 1) ? 80 : (l == 2) ? 320 : 720;
        int off_in  = (l == 0) ? 0 : (l == 1) ? 20 : (l == 2) ? 80 : 180;
        int i = o - off_out;
        int n = i % 20;
        int d = (i / 20) & 3;
        int c = i / 80;
        int e = off_in + c * 20 + n;
        float sum = 0.f;
#pragma unroll
        for (int s = 0; s < 4; s++) {
            float a = acc[s * 320 + e] + acc[(4 + s) * 320 + e] +
                      acc[(8 + s) * 320 + e] + acc[(12 + s) * 320 + e];
            sum = fmaf(sW[d * 4 + s], a, sum);
        }
        outc[o] = sum;
    }
}

extern "C" void kernel_launch(void* const* d_in, const int* in_sizes, int n_in,
                              void* d_out, int out_size) {
    const float4* v0 = (const float4*)d_in[0];
    const float4* v1 = (const float4*)d_in[1];
    const float4* v2 = (const float4*)d_in[2];
    const float4* v3 = (const float4*)d_in[3];
    const float* W = (const float*)d_in[4];
    const int* sp = (const int*)d_in[5];
    const int* dens = (const int*)d_in[6];
    float* out = (float*)d_out;

    hist_kernel<<<(NP + 255) / 256, 256>>>(dens, sp);
    scan_kernel<<<1, 1024>>>();
    scatter_kernel<<<(NP + 255) / 256, 256>>>();
    main_kernel<<<NC, MAINT>>>(v0, v1, v2, v3, W, out);
}